// round 10
// baseline (speedup 1.0000x reference)
#include <cuda_runtime.h>
#include <cuda_bf16.h>
#include <math.h>

// Problem constants
#define BB 128
#define TT 256
#define DD 256
#define HH 256

#define NBLK 128        // 16 groups x (4 layer-1 CTAs + 4 layer-2 CTAs)
#define NGRP 16

typedef unsigned long long ull;

// ---------------- packed f32x2 helpers (Blackwell FFMA2 via PTX) ----------------
__device__ __forceinline__ ull pack2(float lo, float hi) {
    ull r; asm("mov.b64 %0, {%1, %2};" : "=l"(r) : "f"(lo), "f"(hi)); return r;
}
__device__ __forceinline__ void unpack2(float& lo, float& hi, ull v) {
    asm("mov.b64 {%0, %1}, %2;" : "=f"(lo), "=f"(hi) : "l"(v));
}
__device__ __forceinline__ ull fma2(ull a, ull b, ull c) {
    ull d; asm("fma.rn.f32x2 %0, %1, %2, %3;" : "=l"(d) : "l"(a), "l"(b), "l"(c));
    return d;
}

// ---------------- device scratch ----------------
// h tiles stored in GROUP-TILE layout: [t or buf][grp][col*8 + r] (2048 floats/tile)
__device__ float g_pre1[TT * BB * HH];          // pre1[t][b][h] row-major (incl b1)
__device__ float g_h1all[(long)TT * NGRP * 2048];  // h1[t], non-destructive (33.5 MB)
__device__ float g_h2t[2][NGRP * 2048];         // h2 ring, depth 2
__device__ float g_h2rm[BB * HH];               // final forward h2, row-major
__device__ float g_h1bk[BB * HH];
__device__ float g_h2bk[BB * HH];
__device__ unsigned g_f1[NGRP * 32];            // per-group flags, 128B apart
__device__ unsigned g_f2[NGRP * 32];

// ---------------- reset kernel (per-replay determinism) ----------------
__global__ void k_reset() {
    unsigned i = blockIdx.x * blockDim.x + threadIdx.x;
    if (i < NGRP * 32) { g_f1[i] = 0u; g_f2[i] = 0u; }
}

// ---------------- release/acquire flag ops ----------------
__device__ __forceinline__ void signal(unsigned* p) {
    __syncthreads();   // all threads' h stores precede the release
    if (threadIdx.x == 0)
        asm volatile("red.release.gpu.add.u32 [%0], 1;" :: "l"(p) : "memory");
}
__device__ __forceinline__ void waitflag(unsigned* p, unsigned target) {
    if (threadIdx.x == 0) {
        unsigned v;
        do {
            asm volatile("ld.acquire.gpu.u32 %0, [%1];" : "=r"(v) : "l"(p) : "memory");
        } while (v < target);
    }
    __syncthreads();
}

// ---------------- cp.async helpers ----------------
__device__ __forceinline__ unsigned smem_u32(const void* p) {
    unsigned a;
    asm("{ .reg .u64 t; cvta.to.shared.u64 t, %1; cvt.u32.u64 %0, t; }"
        : "=r"(a) : "l"(p));
    return a;
}
__device__ __forceinline__ void cpa16(unsigned saddr, const float* gaddr) {
    asm volatile("cp.async.cg.shared.global [%0], [%1], 16;"
                 :: "r"(saddr), "l"(gaddr) : "memory");
}
#define CPA_COMMIT()  asm volatile("cp.async.commit_group;" ::: "memory")
#define CPA_WAIT(n)   asm volatile("cp.async.wait_group %0;" :: "n"(n) : "memory")

// issue this thread's 16 x 16B chunks of a 256x64-col weight tile into smem
// smem layout sW[k*64 + c]; chunk = tid + i*256: k = chunk>>4, c4 = (chunk&15)*4
__device__ __forceinline__ void load_w_async(unsigned u_sW, const float* __restrict__ W,
                                             int col0, int tid) {
#pragma unroll
    for (int i = 0; i < 16; i++) {
        int chunk = tid + i * 256;
        int k = chunk >> 4;
        int c4 = (chunk & 15) * 4;
        cpa16(u_sW + (unsigned)(k * 64 + c4) * 4, W + (long)k * HH + col0 + c4);
    }
}

// ---------------- generic 64x64 register-blocked fp32 GEMM tile (FFMA2) ----------------
__device__ __forceinline__ void gemm64_body(
    const float* __restrict__ A, long lda,
    const float* __restrict__ A2, int ksplit, long lda2,
    const float* __restrict__ W, long ldw, int wtrans,
    const float* __restrict__ bias,
    float* __restrict__ C, long ldc,
    int K, int row0, int col0, int act,
    float* sA, float* sW)
{
    const int tid = threadIdx.x;
    const int tx = tid & 15;
    const int ty = tid >> 4;
    ull accp[4][2];
#pragma unroll
    for (int i = 0; i < 4; i++) { accp[i][0] = 0ull; accp[i][1] = 0ull; }

#pragma unroll 1
    for (int k0 = 0; k0 < K; k0 += 64) {
        const float* Ak = A; long ldak = lda; int kb = k0;
        if (A2 != nullptr && k0 >= ksplit) { Ak = A2; ldak = lda2; kb = k0 - ksplit; }

        __syncthreads();
#pragma unroll
        for (int p = 0; p < 4; p++) {
            int i = p * 256 + tid;
            int rr = i >> 4;
            int k4 = i & 15;
            float4 v = *(const float4*)(Ak + (long)(row0 + rr) * ldak + kb + k4 * 4);
            *(float4*)(sA + rr * 72 + k4 * 4) = v;
        }
        if (!wtrans) {
#pragma unroll
            for (int p = 0; p < 16; p++) {
                int i = p * 256 + tid;
                int kk = i >> 6, cc = i & 63;
                sW[kk * 72 + cc] = W[(long)(k0 + kk) * ldw + col0 + cc];
            }
        } else {
#pragma unroll
            for (int p = 0; p < 16; p++) {
                int i = p * 256 + tid;
                int kk = i & 63, cc = i >> 6;
                sW[kk * 72 + cc] = W[(long)(col0 + cc) * ldw + k0 + kk];
            }
        }
        __syncthreads();

#pragma unroll
        for (int k = 0; k < 64; k++) {
            ulonglong2 wv = *(const ulonglong2*)(sW + k * 72 + tx * 4);
#pragma unroll
            for (int i = 0; i < 4; i++) {
                float a = sA[(ty * 4 + i) * 72 + k];
                ull ap = pack2(a, a);
                accp[i][0] = fma2(ap, wv.x, accp[i][0]);
                accp[i][1] = fma2(ap, wv.y, accp[i][1]);
            }
        }
    }

#pragma unroll
    for (int i = 0; i < 4; i++) {
        float v0, v1, v2, v3;
        unpack2(v0, v1, accp[i][0]);
        unpack2(v2, v3, accp[i][1]);
        float vv[4] = {v0, v1, v2, v3};
#pragma unroll
        for (int j = 0; j < 4; j++) {
            int rr = row0 + ty * 4 + i;
            int cc = col0 + tx * 4 + j;
            float v = vv[j] + bias[cc];
            if (act) v = tanhf(v);
            C[(long)rr * ldc + cc] = v;
        }
    }
}

// ---------------- K1: precompute pre1[t] = x_t @ Wih_f[0,t] + b_f[0,t] ----------------
__global__ __launch_bounds__(256) void k_pre(
    const float* __restrict__ x, const float* __restrict__ Wih_f,
    const float* __restrict__ b_f)
{
    __shared__ float sA[64 * 72];
    __shared__ float sW[64 * 72];
    int t = blockIdx.y;
    int tile = blockIdx.x;
    int row0 = (tile >> 2) * 64;
    int col0 = (tile & 3) * 64;
    gemm64_body(x + (long)t * DD, (long)TT * DD,
                nullptr, 1 << 30, 0,
                Wih_f + (long)t * DD * HH, HH, 0,
                b_f + (long)t * HH,
                g_pre1 + (long)t * BB * HH, HH,
                DD, row0, col0, /*act=*/0, sA, sW);
}

// ================= K2: layer-split wavefront scan, weights in SMEM =================
// vs R9: weights live in single-buffered SMEM tiles loaded by cp.async.cg
// (16 x 16B per thread per matrix ~ 128 warp-ops/CTA) instead of 64 LDGs per
// thread into registers (512 warp-LDGs/CTA, ~930 cyc LSU floor each). Dots
// read weights with one conflict-free LDS.32 per k. regs 254 -> ~80.

// stage a 2048-float group tile (layout matches smem exactly) — fully coalesced
__device__ __forceinline__ void stage(float* dst, const float* __restrict__ src,
                                      int tid) {
    float4 v0 = __ldcg((const float4*)(src + tid * 8));
    float4 v1 = __ldcg((const float4*)(src + tid * 8 + 4));
    *(float4*)(dst + tid * 8)     = v0;
    *(float4*)(dst + tid * 8 + 4) = v1;
}

// packed dot over this thread's 64-k slice; h tile hsT[k*8+r], weights sW[k*64+c]
__device__ __forceinline__ void dot64s(const float* hsT, const float* sW,
                                       int s, int c,
                                       ull& a01, ull& a23, ull& a45, ull& a67) {
#pragma unroll
    for (int kk = 0; kk < 64; kk++) {
        int k = s * 64 + kk;
        const ulonglong2* p = (const ulonglong2*)(hsT + k * 8);
        ulonglong2 v0 = p[0];
        ulonglong2 v1 = p[1];
        float wk = sW[k * 64 + c];
        ull wp = pack2(wk, wk);
        a01 = fma2(v0.x, wp, a01);
        a23 = fma2(v0.y, wp, a23);
        a45 = fma2(v1.x, wp, a45);
        a67 = fma2(v1.y, wp, a67);
    }
}

// split-K reduce: thread (s,c) gets output rows s and s+4 of column c
__device__ __forceinline__ void reduce2(float* red, ull a01, ull a23, ull a45, ull a67,
                                        int s, int c, float& o0, float& o4) {
    float r[8];
    unpack2(r[0], r[1], a01);
    unpack2(r[2], r[3], a23);
    unpack2(r[4], r[5], a45);
    unpack2(r[6], r[7], a67);
#pragma unroll
    for (int q = 0; q < 8; q++) red[(s * 8 + q) * 64 + c] = r[q];
    __syncthreads();
    o0 = 0.f; o4 = 0.f;
#pragma unroll
    for (int q = 0; q < 4; q++) {
        o0 += red[(q * 8 + s) * 64 + c];
        o4 += red[(q * 8 + s + 4) * 64 + c];
    }
}

// dynamic smem: hsA[2048] hsB[2048] red[2048] sW0[16384] sW1[16384] = 152 KB
#define SMEM_SEQ_BYTES ((2048 * 3 + 16384 * 2) * 4)

__global__ __launch_bounds__(256, 1)
void k_seq(const float* __restrict__ Wih_f, const float* __restrict__ Whh_f,
           const float* __restrict__ b_f)
{
    extern __shared__ float dyn[];
    float* hsA = dyn;
    float* hsB = dyn + 2048;
    float* red = dyn + 4096;
    float* sW0 = dyn + 6144;          // layer1: Whh1 | layer2: Wih2
    float* sW1 = dyn + 6144 + 16384;  // layer2: Whh2
    const unsigned u_sW0 = smem_u32(sW0);
    const unsigned u_sW1 = smem_u32(sW1);

    const int tid = threadIdx.x;
    const int s = tid >> 6;
    const int c = tid & 63;
    const int grp = blockIdx.x >> 3;
    const int sub = blockIdx.x & 7;
    const int layer = sub >> 2;
    const int col0 = (sub & 3) * 64;
    const int row_base = grp * 8;
    const int tidx = (col0 + c) * 8 + s;                 // tile slot (row s)
    const int rm = (row_base + s) * HH + col0 + c;       // row-major (pre1)
    const long gtile = (long)grp * 2048;
    unsigned* f1 = &g_f1[grp * 32];
    unsigned* f2 = &g_f2[grp * 32];

    const float* Whh1 = Whh_f;
    const float* Wih2 = Wih_f + (long)TT * DD * HH;
    const float* Whh2 = Whh_f + (long)TT * HH * HH;
    const float* b2   = b_f + (long)TT * HH;

    if (layer == 0) {
        // ---------------- layer 1 producer ----------------
        load_w_async(u_sW0, Whh1, col0, tid);            // Whh1[0]
        CPA_COMMIT();
        float preA = __ldg(g_pre1 + rm);
        float preB = __ldg(g_pre1 + rm + 4 * HH);
        for (int i = tid; i < 2048; i += 256) hsA[i] = 0.f;   // h1[-1] = 0

#pragma unroll 1
        for (int t = 0; t < TT; t++) {
            const int tn = (t < TT - 1) ? t + 1 : t;
            CPA_WAIT(0);                                  // Whh1[t] landed
            __syncthreads();                              // + hsA staged visible
            ull a01 = 0ull, a23 = 0ull, a45 = 0ull, a67 = 0ull;
            dot64s(hsA, sW0, s, c, a01, a23, a45, a67);
            __syncthreads();                              // all done reading sW0
            load_w_async(u_sW0, Whh1 + (long)tn * HH * HH, col0, tid);
            CPA_COMMIT();
            float r0, r4;
            reduce2(red, a01, a23, a45, a67, s, c, r0, r4);
            float hA = tanhf(preA + r0);
            float hB = tanhf(preB + r4);
            float* dst = g_h1all + ((long)t * NGRP) * 2048 + gtile;
            __stcg(dst + tidx, hA);
            __stcg(dst + tidx + 4, hB);
            signal(f1);
            if (t < TT - 1) {
                waitflag(f1, 4u * (unsigned)(t + 1));
                stage(hsA, g_h1all + ((long)t * NGRP) * 2048 + gtile, tid);
            }
            preA = __ldg(g_pre1 + (long)tn * BB * HH + rm);
            preB = __ldg(g_pre1 + (long)tn * BB * HH + rm + 4 * HH);
        }
    } else {
        // ---------------- layer 2 consumer (lags by one step) ----------------
        load_w_async(u_sW0, Wih2, col0, tid);            // Wih2[0]
        CPA_COMMIT();
        load_w_async(u_sW1, Whh2, col0, tid);            // Whh2[0]
        CPA_COMMIT();
        float bias = __ldg(b2 + col0 + c);
        for (int i = tid; i < 2048; i += 256) hsB[i] = 0.f;   // h2[-1] = 0

#pragma unroll 1
        for (int t = 0; t < TT; t++) {
            const int tn = (t < TT - 1) ? t + 1 : t;

            // h1[t] (layer 1 runs ahead; wait usually satisfied)
            waitflag(f1, 4u * (unsigned)(t + 1));
            stage(hsA, g_h1all + ((long)t * NGRP) * 2048 + gtile, tid);
            CPA_WAIT(1);                                  // Wih2[t] landed
            __syncthreads();
            ull a01 = 0ull, a23 = 0ull, a45 = 0ull, a67 = 0ull;
            dot64s(hsA, sW0, s, c, a01, a23, a45, a67);   // h1[t] @ Wih2[t]
            __syncthreads();
            load_w_async(u_sW0, Wih2 + (long)tn * DD * HH, col0, tid);
            CPA_COMMIT();

            // h2[t-1] — the actual recurrence chain
            if (t > 0) {
                waitflag(f2, 4u * (unsigned)t);
                stage(hsB, g_h2t[(t - 1) & 1] + gtile, tid);
            }
            CPA_WAIT(1);                                  // Whh2[t] landed
            __syncthreads();
            dot64s(hsB, sW1, s, c, a01, a23, a45, a67);   // + h2[t-1] @ Whh2[t]
            __syncthreads();
            load_w_async(u_sW1, Whh2 + (long)tn * HH * HH, col0, tid);
            CPA_COMMIT();

            float r0, r4;
            reduce2(red, a01, a23, a45, a67, s, c, r0, r4);
            float hA = tanhf(bias + r0);
            float hB = tanhf(bias + r4);
            float* dst = g_h2t[t & 1] + gtile;
            __stcg(dst + tidx, hA);
            __stcg(dst + tidx + 4, hB);
            if (t == TT - 1) {                            // final state, row-major
                g_h2rm[rm] = hA;
                g_h2rm[rm + 4 * HH] = hB;
            }
            signal(f2);
            bias = __ldg(b2 + (long)tn * HH + col0 + c);
        }
    }
}

// ---------------- tail kernels: backward single step + fc head ----------------
__global__ __launch_bounds__(256) void k_tail_a(
    const float* __restrict__ x, const float* __restrict__ Wih_b,
    const float* __restrict__ b_b)
{
    __shared__ float sA[64 * 72];
    __shared__ float sW[64 * 72];
    int tile = blockIdx.x;
    int row0 = (tile >> 2) * 64, col0 = (tile & 3) * 64;
    gemm64_body(x + (long)(TT - 1) * DD, (long)TT * DD,
                nullptr, 1 << 30, 0,
                Wih_b + (long)(TT - 1) * DD * HH, HH, 0,
                b_b + (long)(TT - 1) * HH,
                g_h1bk, HH, DD, row0, col0, /*act=*/1, sA, sW);
}

__global__ __launch_bounds__(256) void k_tail_b(
    const float* __restrict__ Wih_b, const float* __restrict__ b_b)
{
    __shared__ float sA[64 * 72];
    __shared__ float sW[64 * 72];
    int tile = blockIdx.x;
    int row0 = (tile >> 2) * 64, col0 = (tile & 3) * 64;
    gemm64_body(g_h1bk, HH,
                nullptr, 1 << 30, 0,
                Wih_b + (long)(TT + TT - 1) * DD * HH, HH, 0,
                b_b + (long)(TT + TT - 1) * HH,
                g_h2bk, HH, HH, row0, col0, /*act=*/1, sA, sW);
}

__global__ __launch_bounds__(256) void k_tail_c(
    const float* __restrict__ fc_w, const float* __restrict__ fc_b,
    float* __restrict__ out)
{
    __shared__ float sA[64 * 72];
    __shared__ float sW[64 * 72];
    int tile = blockIdx.x;
    int row0 = (tile >> 2) * 64, col0 = (tile & 3) * 64;
    gemm64_body(g_h2rm, HH,
                g_h2bk, /*ksplit=*/HH, HH,
                fc_w, 2 * HH, /*wtrans=*/1,
                fc_b,
                out, HH, 2 * HH, row0, col0, /*act=*/0, sA, sW);
}

// ---------------- launcher ----------------
// k_seq stays at launch slot 4 (the profiler's capture slot).
extern "C" void kernel_launch(void* const* d_in, const int* in_sizes, int n_in,
                              void* d_out, int out_size) {
    const float* x     = (const float*)d_in[0];
    const float* Wih_f = (const float*)d_in[1];
    const float* Whh_f = (const float*)d_in[2];
    const float* b_f   = (const float*)d_in[3];
    const float* Wih_b = (const float*)d_in[4];
    // d_in[5] = Whh_b: unused (backward output at t=T-1 starts from h0=0)
    const float* b_b   = (const float*)d_in[6];
    const float* fc_w  = (const float*)d_in[7];
    const float* fc_b  = (const float*)d_in[8];
    float* out = (float*)d_out;
    (void)in_sizes; (void)n_in; (void)out_size;

    static_assert(SMEM_SEQ_BYTES == 155648, "smem layout");
    cudaFuncSetAttribute(k_seq, cudaFuncAttributeMaxDynamicSharedMemorySize,
                         SMEM_SEQ_BYTES);

    k_reset<<<2, 256>>>();
    k_pre<<<dim3(8, TT), 256>>>(x, Wih_f, b_f);
    k_tail_a<<<8, 256>>>(x, Wih_b, b_b);
    k_seq<<<NBLK, 256, SMEM_SEQ_BYTES>>>(Wih_f, Whh_f, b_f);
    k_tail_b<<<8, 256>>>(Wih_b, b_b);
    k_tail_c<<<8, 256>>>(fc_w, fc_b, out);
}

// round 11
// speedup vs baseline: 1.3819x; 1.3819x over previous
#include <cuda_runtime.h>
#include <cuda_bf16.h>
#include <math.h>

// Problem constants
#define BB 128
#define TT 256
#define DD 256
#define HH 256

#define NBLK 128        // 16 groups x (4 layer-1 CTAs + 4 layer-2 CTAs)
#define NGRP 16

typedef unsigned long long ull;

// ---------------- packed f32x2 helpers (Blackwell FFMA2 via PTX) ----------------
__device__ __forceinline__ ull pack2(float lo, float hi) {
    ull r; asm("mov.b64 %0, {%1, %2};" : "=l"(r) : "f"(lo), "f"(hi)); return r;
}
__device__ __forceinline__ void unpack2(float& lo, float& hi, ull v) {
    asm("mov.b64 {%0, %1}, %2;" : "=f"(lo), "=f"(hi) : "l"(v));
}
__device__ __forceinline__ ull fma2(ull a, ull b, ull c) {
    ull d; asm("fma.rn.f32x2 %0, %1, %2, %3;" : "=l"(d) : "l"(a), "l"(b), "l"(c));
    return d;
}

// ---------------- device scratch ----------------
// h tiles stored in GROUP-TILE layout: [t or buf][grp][col*8 + r] (2048 floats/tile)
__device__ float g_pre1[TT * BB * HH];          // pre1[t][b][h] row-major (incl b1)
__device__ float g_h1all[(long)TT * NGRP * 2048];  // h1[t], non-destructive (33.5 MB)
__device__ float g_h2t[2][NGRP * 2048];         // h2 ring, depth 2
__device__ float g_h2rm[BB * HH];               // final forward h2, row-major
__device__ float g_h1bk[BB * HH];
__device__ float g_h2bk[BB * HH];
__device__ unsigned g_f1[NGRP * 32];            // per-group flags, 128B apart
__device__ unsigned g_f2[NGRP * 32];

// ---------------- reset kernel (per-replay determinism) ----------------
__global__ void k_reset() {
    unsigned i = blockIdx.x * blockDim.x + threadIdx.x;
    if (i < NGRP * 32) { g_f1[i] = 0u; g_f2[i] = 0u; }
}

// ---------------- release/acquire flag ops ----------------
__device__ __forceinline__ void signal(unsigned* p) {
    __syncthreads();   // all threads' h stores precede the release
    if (threadIdx.x == 0)
        asm volatile("red.release.gpu.add.u32 [%0], 1;" :: "l"(p) : "memory");
}
__device__ __forceinline__ void waitflag(unsigned* p, unsigned target) {
    if (threadIdx.x == 0) {
        unsigned v;
        do {
            asm volatile("ld.acquire.gpu.u32 %0, [%1];" : "=r"(v) : "l"(p) : "memory");
        } while (v < target);
    }
    __syncthreads();
}

// ---------------- cp.async helpers ----------------
__device__ __forceinline__ unsigned smem_u32(const void* p) {
    unsigned a;
    asm("{ .reg .u64 t; cvta.to.shared.u64 t, %1; cvt.u32.u64 %0, t; }"
        : "=r"(a) : "l"(p));
    return a;
}
__device__ __forceinline__ void cpa16(unsigned saddr, const float* gaddr) {
    asm volatile("cp.async.cg.shared.global [%0], [%1], 16;"
                 :: "r"(saddr), "l"(gaddr) : "memory");
}
#define CPA_COMMIT()  asm volatile("cp.async.commit_group;" ::: "memory")
#define CPA_WAIT(n)   asm volatile("cp.async.wait_group %0;" :: "n"(n) : "memory")

// issue this thread's 16 x 16B chunks of a 256k x 64col weight tile into smem
// smem layout sW[k*64 + c]; chunk = tid + i*256: k = chunk>>4, c4 = (chunk&15)*4
__device__ __forceinline__ void load_w_async(unsigned u_sW, const float* __restrict__ W,
                                             int col0, int tid) {
#pragma unroll
    for (int i = 0; i < 16; i++) {
        int chunk = tid + i * 256;
        int k = chunk >> 4;
        int c4 = (chunk & 15) * 4;
        cpa16(u_sW + (unsigned)(k * 64 + c4) * 4, W + (long)k * HH + col0 + c4);
    }
}

// ---------------- generic 64x64 register-blocked fp32 GEMM tile (FFMA2) ----------------
__device__ __forceinline__ void gemm64_body(
    const float* __restrict__ A, long lda,
    const float* __restrict__ A2, int ksplit, long lda2,
    const float* __restrict__ W, long ldw, int wtrans,
    const float* __restrict__ bias,
    float* __restrict__ C, long ldc,
    int K, int row0, int col0, int act,
    float* sA, float* sW)
{
    const int tid = threadIdx.x;
    const int tx = tid & 15;
    const int ty = tid >> 4;
    ull accp[4][2];
#pragma unroll
    for (int i = 0; i < 4; i++) { accp[i][0] = 0ull; accp[i][1] = 0ull; }

#pragma unroll 1
    for (int k0 = 0; k0 < K; k0 += 64) {
        const float* Ak = A; long ldak = lda; int kb = k0;
        if (A2 != nullptr && k0 >= ksplit) { Ak = A2; ldak = lda2; kb = k0 - ksplit; }

        __syncthreads();
#pragma unroll
        for (int p = 0; p < 4; p++) {
            int i = p * 256 + tid;
            int rr = i >> 4;
            int k4 = i & 15;
            float4 v = *(const float4*)(Ak + (long)(row0 + rr) * ldak + kb + k4 * 4);
            *(float4*)(sA + rr * 72 + k4 * 4) = v;
        }
        if (!wtrans) {
#pragma unroll
            for (int p = 0; p < 16; p++) {
                int i = p * 256 + tid;
                int kk = i >> 6, cc = i & 63;
                sW[kk * 72 + cc] = W[(long)(k0 + kk) * ldw + col0 + cc];
            }
        } else {
#pragma unroll
            for (int p = 0; p < 16; p++) {
                int i = p * 256 + tid;
                int kk = i & 63, cc = i >> 6;
                sW[kk * 72 + cc] = W[(long)(col0 + cc) * ldw + k0 + kk];
            }
        }
        __syncthreads();

#pragma unroll
        for (int k = 0; k < 64; k++) {
            ulonglong2 wv = *(const ulonglong2*)(sW + k * 72 + tx * 4);
#pragma unroll
            for (int i = 0; i < 4; i++) {
                float a = sA[(ty * 4 + i) * 72 + k];
                ull ap = pack2(a, a);
                accp[i][0] = fma2(ap, wv.x, accp[i][0]);
                accp[i][1] = fma2(ap, wv.y, accp[i][1]);
            }
        }
    }

#pragma unroll
    for (int i = 0; i < 4; i++) {
        float v0, v1, v2, v3;
        unpack2(v0, v1, accp[i][0]);
        unpack2(v2, v3, accp[i][1]);
        float vv[4] = {v0, v1, v2, v3};
#pragma unroll
        for (int j = 0; j < 4; j++) {
            int rr = row0 + ty * 4 + i;
            int cc = col0 + tx * 4 + j;
            float v = vv[j] + bias[cc];
            if (act) v = tanhf(v);
            C[(long)rr * ldc + cc] = v;
        }
    }
}

// ---------------- K1: precompute pre1[t] = x_t @ Wih_f[0,t] + b_f[0,t] ----------------
__global__ __launch_bounds__(256) void k_pre(
    const float* __restrict__ x, const float* __restrict__ Wih_f,
    const float* __restrict__ b_f)
{
    __shared__ float sA[64 * 72];
    __shared__ float sW[64 * 72];
    int t = blockIdx.y;
    int tile = blockIdx.x;
    int row0 = (tile >> 2) * 64;
    int col0 = (tile & 3) * 64;
    gemm64_body(x + (long)t * DD, (long)TT * DD,
                nullptr, 1 << 30, 0,
                Wih_f + (long)t * DD * HH, HH, 0,
                b_f + (long)t * HH,
                g_pre1 + (long)t * BB * HH, HH,
                DD, row0, col0, /*act=*/0, sA, sW);
}

// ================= K2: layer-split wavefront, cp.async weights, full-step lead =================
// vs R9: weights via cp.async into SMEM (no LSU burn, regs ~80);
// vs R10: Whh1/Wih2 DOUBLE-buffered (prefetch issued a full step early),
// Whh2 single-buffered but issued right after its last read (also ~full-step
// lead). No extra syncs around weight buffers (write buf != read buf, and the
// single-buffer write is ordered by reduce2's internal barrier).

// stage a 2048-float group tile (layout matches smem exactly) — fully coalesced
__device__ __forceinline__ void stage(float* dst, const float* __restrict__ src,
                                      int tid) {
    float4 v0 = __ldcg((const float4*)(src + tid * 8));
    float4 v1 = __ldcg((const float4*)(src + tid * 8 + 4));
    *(float4*)(dst + tid * 8)     = v0;
    *(float4*)(dst + tid * 8 + 4) = v1;
}

// packed dot over this thread's 64-k slice; h tile hsT[k*8+r], weights sW[k*64+c]
__device__ __forceinline__ void dot64s(const float* hsT, const float* sW,
                                       int s, int c,
                                       ull& a01, ull& a23, ull& a45, ull& a67) {
#pragma unroll
    for (int kk = 0; kk < 64; kk++) {
        int k = s * 64 + kk;
        const ulonglong2* p = (const ulonglong2*)(hsT + k * 8);
        ulonglong2 v0 = p[0];
        ulonglong2 v1 = p[1];
        float wk = sW[k * 64 + c];
        ull wp = pack2(wk, wk);
        a01 = fma2(v0.x, wp, a01);
        a23 = fma2(v0.y, wp, a23);
        a45 = fma2(v1.x, wp, a45);
        a67 = fma2(v1.y, wp, a67);
    }
}

// split-K reduce: thread (s,c) gets output rows s and s+4 of column c
__device__ __forceinline__ void reduce2(float* red, ull a01, ull a23, ull a45, ull a67,
                                        int s, int c, float& o0, float& o4) {
    float r[8];
    unpack2(r[0], r[1], a01);
    unpack2(r[2], r[3], a23);
    unpack2(r[4], r[5], a45);
    unpack2(r[6], r[7], a67);
#pragma unroll
    for (int q = 0; q < 8; q++) red[(s * 8 + q) * 64 + c] = r[q];
    __syncthreads();
    o0 = 0.f; o4 = 0.f;
#pragma unroll
    for (int q = 0; q < 4; q++) {
        o0 += red[(q * 8 + s) * 64 + c];
        o4 += red[(q * 8 + s + 4) * 64 + c];
    }
}

// dynamic smem: hsA[2048] hsB[2048] red[2048] + 3 weight tiles of 16384 floats
// = (6144 + 49152) * 4 = 221184 bytes
#define SMEM_SEQ_BYTES ((2048 * 3 + 16384 * 3) * 4)

__global__ __launch_bounds__(256, 1)
void k_seq(const float* __restrict__ Wih_f, const float* __restrict__ Whh_f,
           const float* __restrict__ b_f)
{
    extern __shared__ float dyn[];
    float* hsA = dyn;
    float* hsB = dyn + 2048;
    float* red = dyn + 4096;
    float* W0  = dyn + 6144;            // L1: Whh1 buf0 | L2: Wih2 buf0
    float* W1  = W0 + 16384;            // L1: Whh1 buf1 | L2: Wih2 buf1
    float* W2  = W0 + 32768;            // L2: Whh2 (single)
    const unsigned u_W0 = smem_u32(W0);
    const unsigned u_W1 = smem_u32(W1);
    const unsigned u_W2 = smem_u32(W2);

    const int tid = threadIdx.x;
    const int s = tid >> 6;
    const int c = tid & 63;
    const int grp = blockIdx.x >> 3;
    const int sub = blockIdx.x & 7;
    const int layer = sub >> 2;
    const int col0 = (sub & 3) * 64;
    const int row_base = grp * 8;
    const int tidx = (col0 + c) * 8 + s;                 // tile slot (row s)
    const int rm = (row_base + s) * HH + col0 + c;       // row-major (pre1)
    const long gtile = (long)grp * 2048;
    unsigned* f1 = &g_f1[grp * 32];
    unsigned* f2 = &g_f2[grp * 32];

    const float* Whh1 = Whh_f;
    const float* Wih2 = Wih_f + (long)TT * DD * HH;
    const float* Whh2 = Whh_f + (long)TT * HH * HH;
    const float* b2   = b_f + (long)TT * HH;

    if (layer == 0) {
        // ---------------- layer 1 producer ----------------
        load_w_async(u_W0, Whh1, col0, tid);             // Whh1[0] -> buf0
        CPA_COMMIT();
        float preA = __ldg(g_pre1 + rm);
        float preB = __ldg(g_pre1 + rm + 4 * HH);
        for (int i = tid; i < 2048; i += 256) hsA[i] = 0.f;   // h1[-1] = 0

#pragma unroll 1
        for (int t = 0; t < TT; t++) {
            const int tn = (t < TT - 1) ? t + 1 : t;
            // prefetch Whh1[t+1] into the other buffer (full-step lead)
            load_w_async(((t + 1) & 1) ? u_W1 : u_W0,
                         Whh1 + (long)tn * HH * HH, col0, tid);
            CPA_COMMIT();
            CPA_WAIT(1);                                  // Whh1[t] landed
            __syncthreads();                              // + hsA staged visible
            const float* sW = (t & 1) ? W1 : W0;
            ull a01 = 0ull, a23 = 0ull, a45 = 0ull, a67 = 0ull;
            dot64s(hsA, sW, s, c, a01, a23, a45, a67);
            float r0, r4;
            reduce2(red, a01, a23, a45, a67, s, c, r0, r4);
            float hA = tanhf(preA + r0);
            float hB = tanhf(preB + r4);
            float* dst = g_h1all + ((long)t * NGRP) * 2048 + gtile;
            __stcg(dst + tidx, hA);
            __stcg(dst + tidx + 4, hB);
            signal(f1);
            if (t < TT - 1) {
                waitflag(f1, 4u * (unsigned)(t + 1));
                stage(hsA, g_h1all + ((long)t * NGRP) * 2048 + gtile, tid);
            }
            preA = __ldg(g_pre1 + (long)tn * BB * HH + rm);
            preB = __ldg(g_pre1 + (long)tn * BB * HH + rm + 4 * HH);
        }
    } else {
        // ---------------- layer 2 consumer (lags by one step) ----------------
        load_w_async(u_W0, Wih2, col0, tid);             // Wih2[0] -> buf0
        CPA_COMMIT();
        load_w_async(u_W2, Whh2, col0, tid);             // Whh2[0]
        CPA_COMMIT();
        float bias = __ldg(b2 + col0 + c);
        for (int i = tid; i < 2048; i += 256) hsB[i] = 0.f;   // h2[-1] = 0

#pragma unroll 1
        for (int t = 0; t < TT; t++) {
            const int tn = (t < TT - 1) ? t + 1 : t;

            // prefetch Wih2[t+1] into the other buffer (full-step lead)
            load_w_async(((t + 1) & 1) ? u_W1 : u_W0,
                         Wih2 + (long)tn * DD * HH, col0, tid);
            CPA_COMMIT();

            // h1[t] (layer 1 runs ahead; wait usually satisfied)
            waitflag(f1, 4u * (unsigned)(t + 1));
            stage(hsA, g_h1all + ((long)t * NGRP) * 2048 + gtile, tid);
            CPA_WAIT(2);                                  // Wih2[t] landed
            __syncthreads();                              // + hsA visible
            const float* sWI = (t & 1) ? W1 : W0;
            ull a01 = 0ull, a23 = 0ull, a45 = 0ull, a67 = 0ull;
            dot64s(hsA, sWI, s, c, a01, a23, a45, a67);   // h1[t] @ Wih2[t]

            // h2[t-1] — the actual recurrence chain
            if (t > 0) {
                waitflag(f2, 4u * (unsigned)t);
                stage(hsB, g_h2t[(t - 1) & 1] + gtile, tid);
            }
            CPA_WAIT(1);                                  // Whh2[t] landed
            __syncthreads();                              // + hsB visible
            dot64s(hsB, W2, s, c, a01, a23, a45, a67);    // + h2[t-1] @ Whh2[t]

            float r0, r4;
            reduce2(red, a01, a23, a45, a67, s, c, r0, r4);  // barrier inside:
                                                             // all W2 reads done
            float hA = tanhf(bias + r0);
            float hB = tanhf(bias + r4);
            float* dst = g_h2t[t & 1] + gtile;
            __stcg(dst + tidx, hA);
            __stcg(dst + tidx + 4, hB);
            if (t == TT - 1) {                            // final state, row-major
                g_h2rm[rm] = hA;
                g_h2rm[rm + 4 * HH] = hB;
            }
            signal(f2);
            // Whh2[t+1] into the single buffer — last read was before reduce2's
            // internal barrier, so this write is safe; lands by next mid-step.
            load_w_async(u_W2, Whh2 + (long)tn * HH * HH, col0, tid);
            CPA_COMMIT();
            bias = __ldg(b2 + (long)tn * HH + col0 + c);
        }
    }
}

// ---------------- tail kernels: backward single step + fc head ----------------
__global__ __launch_bounds__(256) void k_tail_a(
    const float* __restrict__ x, const float* __restrict__ Wih_b,
    const float* __restrict__ b_b)
{
    __shared__ float sA[64 * 72];
    __shared__ float sW[64 * 72];
    int tile = blockIdx.x;
    int row0 = (tile >> 2) * 64, col0 = (tile & 3) * 64;
    gemm64_body(x + (long)(TT - 1) * DD, (long)TT * DD,
                nullptr, 1 << 30, 0,
                Wih_b + (long)(TT - 1) * DD * HH, HH, 0,
                b_b + (long)(TT - 1) * HH,
                g_h1bk, HH, DD, row0, col0, /*act=*/1, sA, sW);
}

__global__ __launch_bounds__(256) void k_tail_b(
    const float* __restrict__ Wih_b, const float* __restrict__ b_b)
{
    __shared__ float sA[64 * 72];
    __shared__ float sW[64 * 72];
    int tile = blockIdx.x;
    int row0 = (tile >> 2) * 64, col0 = (tile & 3) * 64;
    gemm64_body(g_h1bk, HH,
                nullptr, 1 << 30, 0,
                Wih_b + (long)(TT + TT - 1) * DD * HH, HH, 0,
                b_b + (long)(TT + TT - 1) * HH,
                g_h2bk, HH, HH, row0, col0, /*act=*/1, sA, sW);
}

__global__ __launch_bounds__(256) void k_tail_c(
    const float* __restrict__ fc_w, const float* __restrict__ fc_b,
    float* __restrict__ out)
{
    __shared__ float sA[64 * 72];
    __shared__ float sW[64 * 72];
    int tile = blockIdx.x;
    int row0 = (tile >> 2) * 64, col0 = (tile & 3) * 64;
    gemm64_body(g_h2rm, HH,
                g_h2bk, /*ksplit=*/HH, HH,
                fc_w, 2 * HH, /*wtrans=*/1,
                fc_b,
                out, HH, 2 * HH, row0, col0, /*act=*/0, sA, sW);
}

// ---------------- launcher ----------------
// k_seq stays at launch slot 4 (the profiler's capture slot).
extern "C" void kernel_launch(void* const* d_in, const int* in_sizes, int n_in,
                              void* d_out, int out_size) {
    const float* x     = (const float*)d_in[0];
    const float* Wih_f = (const float*)d_in[1];
    const float* Whh_f = (const float*)d_in[2];
    const float* b_f   = (const float*)d_in[3];
    const float* Wih_b = (const float*)d_in[4];
    // d_in[5] = Whh_b: unused (backward output at t=T-1 starts from h0=0)
    const float* b_b   = (const float*)d_in[6];
    const float* fc_w  = (const float*)d_in[7];
    const float* fc_b  = (const float*)d_in[8];
    float* out = (float*)d_out;
    (void)in_sizes; (void)n_in; (void)out_size;

    static_assert(SMEM_SEQ_BYTES == 221184, "smem layout");
    cudaFuncSetAttribute(k_seq, cudaFuncAttributeMaxDynamicSharedMemorySize,
                         SMEM_SEQ_BYTES);

    k_reset<<<2, 256>>>();
    k_pre<<<dim3(8, TT), 256>>>(x, Wih_f, b_f);
    k_tail_a<<<8, 256>>>(x, Wih_b, b_b);
    k_seq<<<NBLK, 256, SMEM_SEQ_BYTES>>>(Wih_f, Whh_f, b_f);
    k_tail_b<<<8, 256>>>(Wih_b, b_b);
    k_tail_c<<<8, 256>>>(fc_w, fc_b, out);
}

// round 12
// speedup vs baseline: 1.4316x; 1.0360x over previous
#include <cuda_runtime.h>
#include <cuda_bf16.h>
#include <math.h>

// Problem constants
#define BB 128
#define TT 256
#define DD 256
#define HH 256

#define NBLK 128        // 16 groups x (4 layer-1 CTAs + 4 layer-2 CTAs)
#define NGRP 16
#define NTH  512        // k_seq threads per CTA (16 warps, 4 per SMSP)

typedef unsigned long long ull;

// ---------------- packed f32x2 helpers (Blackwell FFMA2 via PTX) ----------------
__device__ __forceinline__ ull pack2(float lo, float hi) {
    ull r; asm("mov.b64 %0, {%1, %2};" : "=l"(r) : "f"(lo), "f"(hi)); return r;
}
__device__ __forceinline__ void unpack2(float& lo, float& hi, ull v) {
    asm("mov.b64 {%0, %1}, %2;" : "=f"(lo), "=f"(hi) : "l"(v));
}
__device__ __forceinline__ ull fma2(ull a, ull b, ull c) {
    ull d; asm("fma.rn.f32x2 %0, %1, %2, %3;" : "=l"(d) : "l"(a), "l"(b), "l"(c));
    return d;
}

// ---------------- device scratch ----------------
// h tiles stored in GROUP-TILE layout: [t or buf][grp][col*8 + r] (2048 floats/tile)
__device__ float g_pre1[TT * BB * HH];          // pre1[t][b][h] row-major (incl b1)
__device__ float g_h1all[(long)TT * NGRP * 2048];  // h1[t], non-destructive (33.5 MB)
__device__ float g_h2t[2][NGRP * 2048];         // h2 ring, depth 2
__device__ float g_h2rm[BB * HH];               // final forward h2, row-major
__device__ float g_h1bk[BB * HH];
__device__ float g_h2bk[BB * HH];
__device__ unsigned g_f1[NGRP * 32];            // per-group flags, 128B apart
__device__ unsigned g_f2[NGRP * 32];

// ---------------- reset kernel (per-replay determinism) ----------------
__global__ void k_reset() {
    unsigned i = blockIdx.x * blockDim.x + threadIdx.x;
    if (i < NGRP * 32) { g_f1[i] = 0u; g_f2[i] = 0u; }
}

// ---------------- release/acquire flag ops ----------------
__device__ __forceinline__ void signal(unsigned* p) {
    __syncthreads();   // all threads' h stores precede the release
    if (threadIdx.x == 0)
        asm volatile("red.release.gpu.add.u32 [%0], 1;" :: "l"(p) : "memory");
}
__device__ __forceinline__ void waitflag(unsigned* p, unsigned target) {
    if (threadIdx.x == 0) {
        unsigned v;
        do {
            asm volatile("ld.acquire.gpu.u32 %0, [%1];" : "=r"(v) : "l"(p) : "memory");
        } while (v < target);
    }
    __syncthreads();
}

// ---------------- cp.async helpers ----------------
__device__ __forceinline__ unsigned smem_u32(const void* p) {
    unsigned a;
    asm("{ .reg .u64 t; cvta.to.shared.u64 t, %1; cvt.u32.u64 %0, t; }"
        : "=r"(a) : "l"(p));
    return a;
}
__device__ __forceinline__ void cpa16(unsigned saddr, const float* gaddr) {
    asm volatile("cp.async.cg.shared.global [%0], [%1], 16;"
                 :: "r"(saddr), "l"(gaddr) : "memory");
}
#define CPA_COMMIT()  asm volatile("cp.async.commit_group;" ::: "memory")
#define CPA_WAIT(n)   asm volatile("cp.async.wait_group %0;" :: "n"(n) : "memory")

// issue this thread's 8 x 16B chunks of a 256k x 64col weight tile into smem
// smem layout sW[k*64 + c]; chunk = tid + i*512: k = chunk>>4, c4 = (chunk&15)*4
__device__ __forceinline__ void load_w_async(unsigned u_sW, const float* __restrict__ W,
                                             int col0, int tid) {
#pragma unroll
    for (int i = 0; i < 8; i++) {
        int chunk = tid + i * NTH;
        int k = chunk >> 4;
        int c4 = (chunk & 15) * 4;
        cpa16(u_sW + (unsigned)(k * 64 + c4) * 4, W + (long)k * HH + col0 + c4);
    }
}

// ---------------- generic 64x64 register-blocked fp32 GEMM tile (FFMA2) ----------------
__device__ __forceinline__ void gemm64_body(
    const float* __restrict__ A, long lda,
    const float* __restrict__ A2, int ksplit, long lda2,
    const float* __restrict__ W, long ldw, int wtrans,
    const float* __restrict__ bias,
    float* __restrict__ C, long ldc,
    int K, int row0, int col0, int act,
    float* sA, float* sW)
{
    const int tid = threadIdx.x;
    const int tx = tid & 15;
    const int ty = tid >> 4;
    ull accp[4][2];
#pragma unroll
    for (int i = 0; i < 4; i++) { accp[i][0] = 0ull; accp[i][1] = 0ull; }

#pragma unroll 1
    for (int k0 = 0; k0 < K; k0 += 64) {
        const float* Ak = A; long ldak = lda; int kb = k0;
        if (A2 != nullptr && k0 >= ksplit) { Ak = A2; ldak = lda2; kb = k0 - ksplit; }

        __syncthreads();
#pragma unroll
        for (int p = 0; p < 4; p++) {
            int i = p * 256 + tid;
            int rr = i >> 4;
            int k4 = i & 15;
            float4 v = *(const float4*)(Ak + (long)(row0 + rr) * ldak + kb + k4 * 4);
            *(float4*)(sA + rr * 72 + k4 * 4) = v;
        }
        if (!wtrans) {
#pragma unroll
            for (int p = 0; p < 16; p++) {
                int i = p * 256 + tid;
                int kk = i >> 6, cc = i & 63;
                sW[kk * 72 + cc] = W[(long)(k0 + kk) * ldw + col0 + cc];
            }
        } else {
#pragma unroll
            for (int p = 0; p < 16; p++) {
                int i = p * 256 + tid;
                int kk = i & 63, cc = i >> 6;
                sW[kk * 72 + cc] = W[(long)(col0 + cc) * ldw + k0 + kk];
            }
        }
        __syncthreads();

#pragma unroll
        for (int k = 0; k < 64; k++) {
            ulonglong2 wv = *(const ulonglong2*)(sW + k * 72 + tx * 4);
#pragma unroll
            for (int i = 0; i < 4; i++) {
                float a = sA[(ty * 4 + i) * 72 + k];
                ull ap = pack2(a, a);
                accp[i][0] = fma2(ap, wv.x, accp[i][0]);
                accp[i][1] = fma2(ap, wv.y, accp[i][1]);
            }
        }
    }

#pragma unroll
    for (int i = 0; i < 4; i++) {
        float v0, v1, v2, v3;
        unpack2(v0, v1, accp[i][0]);
        unpack2(v2, v3, accp[i][1]);
        float vv[4] = {v0, v1, v2, v3};
#pragma unroll
        for (int j = 0; j < 4; j++) {
            int rr = row0 + ty * 4 + i;
            int cc = col0 + tx * 4 + j;
            float v = vv[j] + bias[cc];
            if (act) v = tanhf(v);
            C[(long)rr * ldc + cc] = v;
        }
    }
}

// ---------------- K1: precompute pre1[t] = x_t @ Wih_f[0,t] + b_f[0,t] ----------------
__global__ __launch_bounds__(256) void k_pre(
    const float* __restrict__ x, const float* __restrict__ Wih_f,
    const float* __restrict__ b_f)
{
    __shared__ float sA[64 * 72];
    __shared__ float sW[64 * 72];
    int t = blockIdx.y;
    int tile = blockIdx.x;
    int row0 = (tile >> 2) * 64;
    int col0 = (tile & 3) * 64;
    gemm64_body(x + (long)t * DD, (long)TT * DD,
                nullptr, 1 << 30, 0,
                Wih_f + (long)t * DD * HH, HH, 0,
                b_f + (long)t * HH,
                g_pre1 + (long)t * BB * HH, HH,
                DD, row0, col0, /*act=*/0, sA, sW);
}

// ================= K2: layer-split wavefront, 512 threads/CTA =================
// vs R11 (passed, 1475us): identical structure/protocol, but 16 warps per CTA
// (4/SMSP) for 2x latency-hiding. k split 8 ways (s=tid>>6, 32-k slices);
// c=tid&63; each thread finalizes exactly one output element (row s, col c).

// stage a 2048-float group tile (layout matches smem exactly) — fully coalesced
__device__ __forceinline__ void stage(float* dst, const float* __restrict__ src,
                                      int tid) {
    float4 v = __ldcg((const float4*)(src + tid * 4));
    *(float4*)(dst + tid * 4) = v;
}

// packed dot over this thread's 32-k slice; h tile hsT[k*8+r], weights sW[k*64+c]
__device__ __forceinline__ void dot32s(const float* hsT, const float* sW,
                                       int s, int c,
                                       ull& a01, ull& a23, ull& a45, ull& a67) {
#pragma unroll
    for (int kk = 0; kk < 32; kk++) {
        int k = s * 32 + kk;
        const ulonglong2* p = (const ulonglong2*)(hsT + k * 8);
        ulonglong2 v0 = p[0];
        ulonglong2 v1 = p[1];
        float wk = sW[k * 64 + c];
        ull wp = pack2(wk, wk);
        a01 = fma2(v0.x, wp, a01);
        a23 = fma2(v0.y, wp, a23);
        a45 = fma2(v1.x, wp, a45);
        a67 = fma2(v1.y, wp, a67);
    }
}

// split-K reduce over 8 slices: thread (s,c) finalizes output (row=s, col=c)
__device__ __forceinline__ float reduce1(float* red, ull a01, ull a23, ull a45, ull a67,
                                         int s, int c) {
    float r[8];
    unpack2(r[0], r[1], a01);
    unpack2(r[2], r[3], a23);
    unpack2(r[4], r[5], a45);
    unpack2(r[6], r[7], a67);
#pragma unroll
    for (int q = 0; q < 8; q++) red[(s * 8 + q) * 64 + c] = r[q];   // q = row
    __syncthreads();
    float v = 0.f;
#pragma unroll
    for (int q = 0; q < 8; q++) v += red[(q * 8 + s) * 64 + c];     // q = slice
    return v;
}

// dynamic smem: hsA[2048] hsB[2048] red[4096] + 3 weight tiles of 16384 floats
// = (8192 + 49152) * 4 = 229376 bytes (<= 227KB opt-in limit 232448)
#define SMEM_SEQ_BYTES ((2048 * 2 + 4096 + 16384 * 3) * 4)

__global__ __launch_bounds__(NTH, 1)
void k_seq(const float* __restrict__ Wih_f, const float* __restrict__ Whh_f,
           const float* __restrict__ b_f)
{
    extern __shared__ float dyn[];
    float* hsA = dyn;
    float* hsB = dyn + 2048;
    float* red = dyn + 4096;
    float* W0  = dyn + 8192;            // L1: Whh1 buf0 | L2: Wih2 buf0
    float* W1  = W0 + 16384;            // L1: Whh1 buf1 | L2: Wih2 buf1
    float* W2  = W0 + 32768;            // L2: Whh2 (single)
    const unsigned u_W0 = smem_u32(W0);
    const unsigned u_W1 = smem_u32(W1);
    const unsigned u_W2 = smem_u32(W2);

    const int tid = threadIdx.x;
    const int s = tid >> 6;                              // 0..7 k-slice / out row
    const int c = tid & 63;                              // column
    const int grp = blockIdx.x >> 3;
    const int sub = blockIdx.x & 7;
    const int layer = sub >> 2;
    const int col0 = (sub & 3) * 64;
    const int row_base = grp * 8;
    const int tidx = (col0 + c) * 8 + s;                 // tile slot (row s)
    const int rm = (row_base + s) * HH + col0 + c;       // row-major (pre1)
    const long gtile = (long)grp * 2048;
    unsigned* f1 = &g_f1[grp * 32];
    unsigned* f2 = &g_f2[grp * 32];

    const float* Whh1 = Whh_f;
    const float* Wih2 = Wih_f + (long)TT * DD * HH;
    const float* Whh2 = Whh_f + (long)TT * HH * HH;
    const float* b2   = b_f + (long)TT * HH;

    if (layer == 0) {
        // ---------------- layer 1 producer ----------------
        load_w_async(u_W0, Whh1, col0, tid);             // Whh1[0] -> buf0
        CPA_COMMIT();
        float pre = __ldg(g_pre1 + rm);
        for (int i = tid; i < 2048; i += NTH) hsA[i] = 0.f;   // h1[-1] = 0

#pragma unroll 1
        for (int t = 0; t < TT; t++) {
            const int tn = (t < TT - 1) ? t + 1 : t;
            // prefetch Whh1[t+1] into the other buffer (full-step lead)
            load_w_async(((t + 1) & 1) ? u_W1 : u_W0,
                         Whh1 + (long)tn * HH * HH, col0, tid);
            CPA_COMMIT();
            CPA_WAIT(1);                                  // Whh1[t] landed
            __syncthreads();                              // + hsA staged visible
            const float* sW = (t & 1) ? W1 : W0;
            ull a01 = 0ull, a23 = 0ull, a45 = 0ull, a67 = 0ull;
            dot32s(hsA, sW, s, c, a01, a23, a45, a67);
            float r0 = reduce1(red, a01, a23, a45, a67, s, c);
            float hA = tanhf(pre + r0);
            float* dst = g_h1all + ((long)t * NGRP) * 2048 + gtile;
            __stcg(dst + tidx, hA);
            signal(f1);
            if (t < TT - 1) {
                waitflag(f1, 4u * (unsigned)(t + 1));
                stage(hsA, g_h1all + ((long)t * NGRP) * 2048 + gtile, tid);
            }
            pre = __ldg(g_pre1 + (long)tn * BB * HH + rm);
        }
    } else {
        // ---------------- layer 2 consumer (lags by one step) ----------------
        load_w_async(u_W0, Wih2, col0, tid);             // Wih2[0] -> buf0
        CPA_COMMIT();
        load_w_async(u_W2, Whh2, col0, tid);             // Whh2[0]
        CPA_COMMIT();
        float bias = __ldg(b2 + col0 + c);
        for (int i = tid; i < 2048; i += NTH) hsB[i] = 0.f;   // h2[-1] = 0

#pragma unroll 1
        for (int t = 0; t < TT; t++) {
            const int tn = (t < TT - 1) ? t + 1 : t;

            // prefetch Wih2[t+1] into the other buffer (full-step lead)
            load_w_async(((t + 1) & 1) ? u_W1 : u_W0,
                         Wih2 + (long)tn * DD * HH, col0, tid);
            CPA_COMMIT();

            // h1[t] (layer 1 runs ahead; wait usually satisfied)
            waitflag(f1, 4u * (unsigned)(t + 1));
            stage(hsA, g_h1all + ((long)t * NGRP) * 2048 + gtile, tid);
            CPA_WAIT(2);                                  // Wih2[t] landed
            __syncthreads();                              // + hsA visible
            const float* sWI = (t & 1) ? W1 : W0;
            ull a01 = 0ull, a23 = 0ull, a45 = 0ull, a67 = 0ull;
            dot32s(hsA, sWI, s, c, a01, a23, a45, a67);   // h1[t] @ Wih2[t]

            // h2[t-1] — the actual recurrence chain
            if (t > 0) {
                waitflag(f2, 4u * (unsigned)t);
                stage(hsB, g_h2t[(t - 1) & 1] + gtile, tid);
            }
            CPA_WAIT(1);                                  // Whh2[t] landed
            __syncthreads();                              // + hsB visible
            dot32s(hsB, W2, s, c, a01, a23, a45, a67);    // + h2[t-1] @ Whh2[t]

            float r0 = reduce1(red, a01, a23, a45, a67, s, c);  // barrier inside:
                                                                // all W2 reads done
            float hA = tanhf(bias + r0);
            float* dst = g_h2t[t & 1] + gtile;
            __stcg(dst + tidx, hA);
            if (t == TT - 1) g_h2rm[rm] = hA;             // final state, row-major
            signal(f2);
            // Whh2[t+1] into the single buffer — last read was before reduce1's
            // internal barrier, so this write is safe; lands by next mid-step.
            load_w_async(u_W2, Whh2 + (long)tn * HH * HH, col0, tid);
            CPA_COMMIT();
            bias = __ldg(b2 + (long)tn * HH + col0 + c);
        }
    }
}

// ---------------- tail kernels: backward single step + fc head ----------------
__global__ __launch_bounds__(256) void k_tail_a(
    const float* __restrict__ x, const float* __restrict__ Wih_b,
    const float* __restrict__ b_b)
{
    __shared__ float sA[64 * 72];
    __shared__ float sW[64 * 72];
    int tile = blockIdx.x;
    int row0 = (tile >> 2) * 64, col0 = (tile & 3) * 64;
    gemm64_body(x + (long)(TT - 1) * DD, (long)TT * DD,
                nullptr, 1 << 30, 0,
                Wih_b + (long)(TT - 1) * DD * HH, HH, 0,
                b_b + (long)(TT - 1) * HH,
                g_h1bk, HH, DD, row0, col0, /*act=*/1, sA, sW);
}

__global__ __launch_bounds__(256) void k_tail_b(
    const float* __restrict__ Wih_b, const float* __restrict__ b_b)
{
    __shared__ float sA[64 * 72];
    __shared__ float sW[64 * 72];
    int tile = blockIdx.x;
    int row0 = (tile >> 2) * 64, col0 = (tile & 3) * 64;
    gemm64_body(g_h1bk, HH,
                nullptr, 1 << 30, 0,
                Wih_b + (long)(TT + TT - 1) * DD * HH, HH, 0,
                b_b + (long)(TT + TT - 1) * HH,
                g_h2bk, HH, HH, row0, col0, /*act=*/1, sA, sW);
}

__global__ __launch_bounds__(256) void k_tail_c(
    const float* __restrict__ fc_w, const float* __restrict__ fc_b,
    float* __restrict__ out)
{
    __shared__ float sA[64 * 72];
    __shared__ float sW[64 * 72];
    int tile = blockIdx.x;
    int row0 = (tile >> 2) * 64, col0 = (tile & 3) * 64;
    gemm64_body(g_h2rm, HH,
                g_h2bk, /*ksplit=*/HH, HH,
                fc_w, 2 * HH, /*wtrans=*/1,
                fc_b,
                out, HH, 2 * HH, row0, col0, /*act=*/0, sA, sW);
}

// ---------------- launcher ----------------
// k_seq stays at launch slot 4 (the profiler's capture slot).
extern "C" void kernel_launch(void* const* d_in, const int* in_sizes, int n_in,
                              void* d_out, int out_size) {
    const float* x     = (const float*)d_in[0];
    const float* Wih_f = (const float*)d_in[1];
    const float* Whh_f = (const float*)d_in[2];
    const float* b_f   = (const float*)d_in[3];
    const float* Wih_b = (const float*)d_in[4];
    // d_in[5] = Whh_b: unused (backward output at t=T-1 starts from h0=0)
    const float* b_b   = (const float*)d_in[6];
    const float* fc_w  = (const float*)d_in[7];
    const float* fc_b  = (const float*)d_in[8];
    float* out = (float*)d_out;
    (void)in_sizes; (void)n_in; (void)out_size;

    static_assert(SMEM_SEQ_BYTES == 229376, "smem layout");
    cudaFuncSetAttribute(k_seq, cudaFuncAttributeMaxDynamicSharedMemorySize,
                         SMEM_SEQ_BYTES);

    k_reset<<<2, 256>>>();
    k_pre<<<dim3(8, TT), 256>>>(x, Wih_f, b_f);
    k_tail_a<<<8, 256>>>(x, Wih_b, b_b);
    k_seq<<<NBLK, NTH, SMEM_SEQ_BYTES>>>(Wih_f, Whh_f, b_f);
    k_tail_b<<<8, 256>>>(Wih_b, b_b);
    k_tail_c<<<8, 256>>>(fc_w, fc_b, out);
}